// round 6
// baseline (speedup 1.0000x reference)
#include <cuda_runtime.h>

#define N_NODES 100000
#define N_EDGES 600000
#define E_TOT   700000      // edges + self loops
#define D       128
#define SCAN_B  1024
#define NB      ((N_NODES + SCAN_B - 1) / SCAN_B)   // 98
#define MEAN_B  256

// ---------------- scratch: __device__ globals only (no allocations) ----------------
__device__ __align__(16) float g_h[(size_t)N_NODES * D];   // post-GEMM features
__device__ __align__(16) float g_o[(size_t)N_NODES * D];   // layer output
__device__ float g_as[N_NODES];
__device__ float g_ad[N_NODES];
__device__ int   g_deg[N_NODES];
__device__ int   g_incl[N_NODES];
__device__ int   g_bsum[NB];
__device__ int   g_bpre[NB];
__device__ int   g_rp[N_NODES + 1];   // CSR row_ptr (by dst)
__device__ int   g_cur[N_NODES];      // scatter cursor
__device__ int   g_col[E_TOT];        // src node per incoming edge
__device__ float g_part[MEAN_B * D];

// ---------------- CSR build (edge_index is int32: [src x E | dst x E]) ------------
__global__ void k_deg_init() {
    int i = blockIdx.x * blockDim.x + threadIdx.x;
    if (i < N_NODES) g_deg[i] = 1;   // self loop
}

__global__ void k_deg_count(const int* __restrict__ ei) {
    int e = blockIdx.x * blockDim.x + threadIdx.x;
    if (e < N_EDGES) {
        int d = ei[N_EDGES + e];
        if ((unsigned)d < N_NODES) atomicAdd(&g_deg[d], 1);
    }
}

__global__ void __launch_bounds__(SCAN_B) k_scan1() {
    __shared__ int s[SCAN_B];
    int tl = threadIdx.x;
    int t  = blockIdx.x * SCAN_B + tl;
    int v  = (t < N_NODES) ? g_deg[t] : 0;
    s[tl] = v;
    __syncthreads();
    #pragma unroll
    for (int off = 1; off < SCAN_B; off <<= 1) {
        int add = (tl >= off) ? s[tl - off] : 0;
        __syncthreads();
        s[tl] += add;
        __syncthreads();
    }
    if (t < N_NODES) g_incl[t] = s[tl];
    if (tl == SCAN_B - 1) g_bsum[blockIdx.x] = s[tl];
}

__global__ void k_scan2() {
    __shared__ int s[128];
    int t = threadIdx.x;
    int v = (t < NB) ? g_bsum[t] : 0;
    s[t] = v;
    __syncthreads();
    #pragma unroll
    for (int off = 1; off < 128; off <<= 1) {
        int add = (t >= off) ? s[t - off] : 0;
        __syncthreads();
        s[t] += add;
        __syncthreads();
    }
    if (t < NB) g_bpre[t] = s[t] - v;   // exclusive prefix of block sums
}

__global__ void k_scan3() {
    int t = blockIdx.x * blockDim.x + threadIdx.x;
    if (t < N_NODES) {
        int S = g_incl[t] + g_bpre[t / SCAN_B];   // inclusive prefix
        g_rp[t + 1] = S;
        g_cur[t]    = S - g_deg[t];
        if (t == 0) g_rp[0] = 0;
    }
}

__global__ void k_scatter(const int* __restrict__ ei) {
    int e = blockIdx.x * blockDim.x + threadIdx.x;
    if (e >= E_TOT) return;
    int s, d;
    if (e < N_EDGES) { s = ei[e]; d = ei[N_EDGES + e]; }
    else             { s = e - N_EDGES; d = s; }
    if ((unsigned)s >= N_NODES || (unsigned)d >= N_NODES) return;
    int pos = atomicAdd(&g_cur[d], 1);
    g_col[pos] = s;
}

// ---------------- GEMM: g_h = X*W, g_as = h.a_src, g_ad = h.a_dst ----------------
// 256 thr, 64 rows x 128 cols; static smem: Xs 32KB + Wc 8KB = 40KB
__global__ void __launch_bounds__(256) k_gemm(
    const float* __restrict__ Xext, int use_ext,
    const float* __restrict__ W,
    const float* __restrict__ avs, const float* __restrict__ avd)
{
    __shared__ float Xs[64 * D];      // 64 rows x 128
    __shared__ float Wc[16 * D];      // k-chunk 16 x 128

    const float* X = use_ext ? Xext : g_o;
    const int tid  = threadIdx.x;
    const int row0 = blockIdx.x * 64;

    // stage X tile once
    {
        float4* Xs4 = (float4*)Xs;
        const float4* X4 = (const float4*)X;
        #pragma unroll
        for (int i = tid; i < 64 * D / 4; i += 256) {
            int r  = i / (D / 4);
            int gr = row0 + r;
            Xs4[i] = (gr < N_NODES) ? X4[(size_t)gr * (D / 4) + (i % (D / 4))]
                                    : make_float4(0.f, 0.f, 0.f, 0.f);
        }
    }

    const int warp  = tid >> 5;
    const int lane  = tid & 31;
    const int rbase = warp * 8;
    const int c0    = lane * 4;

    float acc[8][4];
    #pragma unroll
    for (int i = 0; i < 8; i++)
        #pragma unroll
        for (int j = 0; j < 4; j++) acc[i][j] = 0.f;

    for (int kc = 0; kc < D / 16; kc++) {
        __syncthreads();
        // load W chunk rows [kc*16, kc*16+16)
        {
            float4* Wc4 = (float4*)Wc;
            const float4* W4 = (const float4*)W + (size_t)kc * 16 * (D / 4);
            #pragma unroll
            for (int i = tid; i < 16 * D / 4; i += 256) Wc4[i] = W4[i];
        }
        __syncthreads();

        #pragma unroll
        for (int k = 0; k < 16; k++) {
            float4 wv = *(const float4*)&Wc[k * D + c0];
            int kg = kc * 16 + k;
            #pragma unroll
            for (int i = 0; i < 8; i++) {
                float xv = Xs[(rbase + i) * D + kg];
                acc[i][0] = fmaf(xv, wv.x, acc[i][0]);
                acc[i][1] = fmaf(xv, wv.y, acc[i][1]);
                acc[i][2] = fmaf(xv, wv.z, acc[i][2]);
                acc[i][3] = fmaf(xv, wv.w, acc[i][3]);
            }
        }
    }

    const float4 as4 = *(const float4*)&avs[c0];
    const float4 ad4 = *(const float4*)&avd[c0];

    #pragma unroll
    for (int i = 0; i < 8; i++) {
        int gr = row0 + rbase + i;
        if (gr < N_NODES) {
            *(float4*)&g_h[(size_t)gr * D + c0] =
                make_float4(acc[i][0], acc[i][1], acc[i][2], acc[i][3]);
        }
        float ps = acc[i][0]*as4.x + acc[i][1]*as4.y + acc[i][2]*as4.z + acc[i][3]*as4.w;
        float pd = acc[i][0]*ad4.x + acc[i][1]*ad4.y + acc[i][2]*ad4.z + acc[i][3]*ad4.w;
        #pragma unroll
        for (int off = 16; off; off >>= 1) {
            ps += __shfl_xor_sync(0xffffffffu, ps, off);
            pd += __shfl_xor_sync(0xffffffffu, pd, off);
        }
        if (lane == 0 && gr < N_NODES) { g_as[gr] = ps; g_ad[gr] = pd; }
    }
}

// ---------------- warp-per-node single-pass softmax-aggregate ----------------
// softmax is shift-invariant; |e| <= ~15 here so exp(e) cannot overflow fp32.
// One pass: acc = sum w_j * h[col_j], wsum = sum w_j; out = acc/wsum + b.
__global__ void __launch_bounds__(256) k_node_agg(int do_relu, const float* __restrict__ b)
{
    int node = (blockIdx.x * blockDim.x + threadIdx.x) >> 5;
    int lane = threadIdx.x & 31;
    if (node >= N_NODES) return;

    int beg = g_rp[node];
    int end = g_rp[node + 1];
    float ad = g_ad[node];

    float4 acc = make_float4(0.f, 0.f, 0.f, 0.f);
    float wsum = 0.f;

    for (int base = beg; base < end; base += 32) {
        int j = base + lane;
        float w = 0.f;
        int   col = 0;
        if (j < end) {
            col = g_col[j];
            float e = g_as[col] + ad;
            e = fmaxf(e, 0.f) + 0.2f * fminf(e, 0.f);   // leaky_relu(0.2)
            w = __expf(e);
        }
        wsum += w;
        int n = min(32, end - base);
        for (int t = 0; t < n; t++) {
            float wj = __shfl_sync(0xffffffffu, w,   t);
            int   cj = __shfl_sync(0xffffffffu, col, t);
            float4 hv = *(const float4*)&g_h[(size_t)cj * D + lane * 4];
            acc.x = fmaf(wj, hv.x, acc.x);
            acc.y = fmaf(wj, hv.y, acc.y);
            acc.z = fmaf(wj, hv.z, acc.z);
            acc.w = fmaf(wj, hv.w, acc.w);
        }
    }

    // reduce wsum across lanes (each lane holds partial over its edge subset)
    #pragma unroll
    for (int off = 16; off; off >>= 1)
        wsum += __shfl_xor_sync(0xffffffffu, wsum, off);
    float inv = 1.f / wsum;

    const float4 b4 = *(const float4*)&b[lane * 4];
    acc.x = fmaf(acc.x, inv, b4.x);
    acc.y = fmaf(acc.y, inv, b4.y);
    acc.z = fmaf(acc.z, inv, b4.z);
    acc.w = fmaf(acc.w, inv, b4.w);
    if (do_relu) {
        acc.x = fmaxf(acc.x, 0.f); acc.y = fmaxf(acc.y, 0.f);
        acc.z = fmaxf(acc.z, 0.f); acc.w = fmaxf(acc.w, 0.f);
    }
    *(float4*)&g_o[(size_t)node * D + lane * 4] = acc;
}

// ---------------- mean over nodes ----------------
__global__ void k_mean1() {
    int c = threadIdx.x;   // 128 threads = 128 cols
    float acc = 0.f;
    for (int r = blockIdx.x; r < N_NODES; r += MEAN_B)
        acc += g_o[(size_t)r * D + c];
    g_part[blockIdx.x * D + c] = acc;
}

__global__ void k_mean2(float* __restrict__ out) {
    int c = threadIdx.x;
    float s = 0.f;
    for (int i = 0; i < MEAN_B; i++) s += g_part[i * D + c];
    out[c] = s * (1.0f / N_NODES);
}

// ---------------- driver: kernel launches ONLY ----------------
extern "C" void kernel_launch(void* const* d_in, const int* in_sizes, int n_in,
                              void* d_out, int out_size)
{
    const float* x   = (const float*)d_in[0];
    const int*   ei  = (const int*)d_in[1];      // int32: [src x E | dst x E]
    const float* W1  = (const float*)d_in[2];
    const float* as1 = (const float*)d_in[3];
    const float* ad1 = (const float*)d_in[4];
    const float* b1  = (const float*)d_in[5];
    const float* W2  = (const float*)d_in[6];
    const float* as2 = (const float*)d_in[7];
    const float* ad2 = (const float*)d_in[8];
    const float* b2  = (const float*)d_in[9];
    float* out = (float*)d_out;

    // CSR build (identical for both layers)
    k_deg_init <<<(N_NODES + 255) / 256, 256>>>();
    k_deg_count<<<(N_EDGES + 255) / 256, 256>>>(ei);
    k_scan1    <<<NB, SCAN_B>>>();
    k_scan2    <<<1, 128>>>();
    k_scan3    <<<(N_NODES + 255) / 256, 256>>>();
    k_scatter  <<<(E_TOT + 255) / 256, 256>>>(ei);

    // layer 1: x -> g_h -> g_o (relu)
    k_gemm    <<<(N_NODES + 63) / 64, 256>>>(x, 1, W1, as1, ad1);
    k_node_agg<<<(N_NODES * 32 + 255) / 256, 256>>>(1, b1);

    // layer 2: g_o -> g_h -> g_o
    k_gemm    <<<(N_NODES + 63) / 64, 256>>>(nullptr, 0, W2, as2, ad2);
    k_node_agg<<<(N_NODES * 32 + 255) / 256, 256>>>(0, b2);

    // mean over nodes -> d_out[128]
    k_mean1<<<MEAN_B, D>>>();
    k_mean2<<<1, D>>>(out);
}

// round 8
// speedup vs baseline: 1.3118x; 1.3118x over previous
#include <cuda_runtime.h>
#include <cuda_bf16.h>
#include <cstdint>

#define N_NODES 100000
#define N_EDGES 600000
#define E_TOT   700000      // edges + self loops
#define D       128
#define SCAN_B  1024
#define NB      ((N_NODES + SCAN_B - 1) / SCAN_B)   // 98
#define MEAN_B  256
#define N_TILES ((N_NODES + 127) / 128)              // 782

#define XPAD    136                                   // padded row length (bf16 elems)
#define TILE_B  (128 * XPAD * 2)                      // 34816 bytes per bf16 tile
// dynamic smem layout (bytes)
#define SM_XHI  0
#define SM_XLO  (TILE_B)
#define SM_WHI  (2 * TILE_B)
#define SM_WLO  (3 * TILE_B)
#define SM_ALPH (4 * TILE_B)                          // as[128][2], ad[128][2] floats
#define SM_TOT  (4 * TILE_B + 2048)                   // 141312

// ---------------- scratch: __device__ globals only (no allocations) ----------------
__device__ __align__(16) float g_h[(size_t)N_NODES * D];   // post-GEMM features
__device__ __align__(16) float g_o[(size_t)N_NODES * D];   // layer output
__device__ __align__(16) unsigned short g_wthi[128 * XPAD]; // W^T hi bf16, padded rows
__device__ __align__(16) unsigned short g_wtlo[128 * XPAD]; // W^T lo bf16
__device__ float g_as[N_NODES];
__device__ float g_ad[N_NODES];
__device__ int   g_deg[N_NODES];
__device__ int   g_incl[N_NODES];
__device__ int   g_bsum[NB];
__device__ int   g_bpre[NB];
__device__ int   g_rp[N_NODES + 1];   // CSR row_ptr (by dst)
__device__ int   g_cur[N_NODES];      // scatter cursor
__device__ int   g_col[E_TOT];        // src node per incoming edge
__device__ float g_part[MEAN_B * D];

// ---------------- mma helper: m16n8k16 row.col f32.bf16.bf16.f32 ----------------
__device__ __forceinline__ void mma_bf16(float* c, uint32_t a0, uint32_t a1, uint32_t a2,
                                         uint32_t a3, uint32_t b0, uint32_t b1) {
    asm volatile(
        "mma.sync.aligned.m16n8k16.row.col.f32.bf16.bf16.f32 "
        "{%0,%1,%2,%3}, {%4,%5,%6,%7}, {%8,%9}, {%0,%1,%2,%3};"
        : "+f"(c[0]), "+f"(c[1]), "+f"(c[2]), "+f"(c[3])
        : "r"(a0), "r"(a1), "r"(a2), "r"(a3), "r"(b0), "r"(b1));
}
__device__ __forceinline__ uint32_t pack_bf16(float x, float y) {
    __nv_bfloat16 bx = __float2bfloat16(x), by = __float2bfloat16(y);
    unsigned short ux = *(unsigned short*)&bx, uy = *(unsigned short*)&by;
    return (uint32_t)ux | ((uint32_t)uy << 16);
}

// ---------------- CSR build (edge_index is int32: [src x E | dst x E]) ------------
__global__ void k_deg_init() {
    int i = blockIdx.x * blockDim.x + threadIdx.x;
    if (i < N_NODES) g_deg[i] = 1;   // self loop
}

__global__ void k_deg_count(const int* __restrict__ ei) {
    int e = blockIdx.x * blockDim.x + threadIdx.x;
    if (e < N_EDGES) {
        int d = ei[N_EDGES + e];
        if ((unsigned)d < N_NODES) atomicAdd(&g_deg[d], 1);
    }
}

__global__ void __launch_bounds__(SCAN_B) k_scan1() {
    __shared__ int s[SCAN_B];
    int tl = threadIdx.x;
    int t  = blockIdx.x * SCAN_B + tl;
    int v  = (t < N_NODES) ? g_deg[t] : 0;
    s[tl] = v;
    __syncthreads();
    #pragma unroll
    for (int off = 1; off < SCAN_B; off <<= 1) {
        int add = (tl >= off) ? s[tl - off] : 0;
        __syncthreads();
        s[tl] += add;
        __syncthreads();
    }
    if (t < N_NODES) g_incl[t] = s[tl];
    if (tl == SCAN_B - 1) g_bsum[blockIdx.x] = s[tl];
}

__global__ void k_scan2() {
    __shared__ int s[128];
    int t = threadIdx.x;
    int v = (t < NB) ? g_bsum[t] : 0;
    s[t] = v;
    __syncthreads();
    #pragma unroll
    for (int off = 1; off < 128; off <<= 1) {
        int add = (t >= off) ? s[t - off] : 0;
        __syncthreads();
        s[t] += add;
        __syncthreads();
    }
    if (t < NB) g_bpre[t] = s[t] - v;   // exclusive prefix of block sums
}

__global__ void k_scan3() {
    int t = blockIdx.x * blockDim.x + threadIdx.x;
    if (t < N_NODES) {
        int S = g_incl[t] + g_bpre[t / SCAN_B];   // inclusive prefix
        g_rp[t + 1] = S;
        g_cur[t]    = S - g_deg[t];
        if (t == 0) g_rp[0] = 0;
    }
}

__global__ void k_scatter(const int* __restrict__ ei) {
    int e = blockIdx.x * blockDim.x + threadIdx.x;
    if (e >= E_TOT) return;
    int s, d;
    if (e < N_EDGES) { s = ei[e]; d = ei[N_EDGES + e]; }
    else             { s = e - N_EDGES; d = s; }
    if ((unsigned)s >= N_NODES || (unsigned)d >= N_NODES) return;
    int pos = atomicAdd(&g_cur[d], 1);
    g_col[pos] = s;
}

// ---------------- W split+transpose: g_wt{hi,lo}[n][k] = split(W[k][n]) ------------
__global__ void k_wsplit(const float* __restrict__ W) {
    int t = blockIdx.x * blockDim.x + threadIdx.x;
    if (t >= D * D) return;
    int n = t >> 7, k = t & 127;
    float v = W[k * D + n];
    __nv_bfloat16 hb = __float2bfloat16(v);
    float hf = __bfloat162float(hb);
    __nv_bfloat16 lb = __float2bfloat16(v - hf);
    g_wthi[n * XPAD + k] = *(unsigned short*)&hb;
    g_wtlo[n * XPAD + k] = *(unsigned short*)&lb;
}

// ---------------- HMMA GEMM: H = X*W (split-2 bf16, fp32 accum) --------------------
// 256 thr / block; 128-row tile; 8 warps = 4(m) x 2(n), warp tile 32x64
__global__ void __launch_bounds__(256) k_gemm(
    const float* __restrict__ Xext, int use_ext,
    const float* __restrict__ avs, const float* __restrict__ avd)
{
    extern __shared__ unsigned char smem[];
    unsigned short* Xhi = (unsigned short*)(smem + SM_XHI);
    unsigned short* Xlo = (unsigned short*)(smem + SM_XLO);
    unsigned short* Whi = (unsigned short*)(smem + SM_WHI);
    unsigned short* Wlo = (unsigned short*)(smem + SM_WLO);
    float* as_s = (float*)(smem + SM_ALPH);          // [128][2]
    float* ad_s = (float*)(smem + SM_ALPH + 1024);   // [128][2]

    const int tid  = threadIdx.x;
    const int warp = tid >> 5;
    const int lane = tid & 31;
    const int lq   = lane & 3;      // thread-in-group
    const int lr   = lane >> 2;     // group id
    const int row0 = blockIdx.x * 128;
    const int mrow0 = (warp >> 1) * 32;
    const int ncol0 = (warp & 1) * 64;
    const float* X = use_ext ? Xext : g_o;

    // stage X (fp32, coalesced float4) -> split to bf16 hi/lo in padded smem
    {
        const float4* X4 = (const float4*)X;
        #pragma unroll
        for (int i = tid; i < 128 * 32; i += 256) {
            int r = i >> 5, c4 = i & 31;
            int gr = row0 + r;
            float4 v = (gr < N_NODES) ? X4[(size_t)gr * 32 + c4]
                                      : make_float4(0.f, 0.f, 0.f, 0.f);
            __nv_bfloat16 h0 = __float2bfloat16(v.x), h1 = __float2bfloat16(v.y);
            __nv_bfloat16 h2 = __float2bfloat16(v.z), h3 = __float2bfloat16(v.w);
            float f0 = __bfloat162float(h0), f1 = __bfloat162float(h1);
            float f2 = __bfloat162float(h2), f3 = __bfloat162float(h3);
            uint2 hw, lw;
            hw.x = pack_bf16(v.x, v.y); // hi parts via pack of already-rounded? need hi only
            // pack hi
            {
                unsigned short u0 = *(unsigned short*)&h0, u1 = *(unsigned short*)&h1;
                unsigned short u2 = *(unsigned short*)&h2, u3 = *(unsigned short*)&h3;
                hw.x = (uint32_t)u0 | ((uint32_t)u1 << 16);
                hw.y = (uint32_t)u2 | ((uint32_t)u3 << 16);
            }
            lw.x = pack_bf16(v.x - f0, v.y - f1);
            lw.y = pack_bf16(v.z - f2, v.w - f3);
            int off = r * XPAD + c4 * 4;
            *(uint2*)&Xhi[off] = hw;
            *(uint2*)&Xlo[off] = lw;
        }
    }
    // stage pre-split W tiles (linear 16B copies incl. pad)
    {
        const uint4* wh = (const uint4*)g_wthi;
        const uint4* wl = (const uint4*)g_wtlo;
        uint4* sh = (uint4*)Whi;
        uint4* sl = (uint4*)Wlo;
        #pragma unroll
        for (int i = tid; i < TILE_B / 16; i += 256) { sh[i] = wh[i]; sl[i] = wl[i]; }
    }
    __syncthreads();

    float acc[2][8][4];
    #pragma unroll
    for (int mt = 0; mt < 2; mt++)
        #pragma unroll
        for (int nt = 0; nt < 8; nt++)
            #pragma unroll
            for (int j = 0; j < 4; j++) acc[mt][nt][j] = 0.f;

    #pragma unroll
    for (int ks = 0; ks < 8; ks++) {
        const int kc = ks * 16 + lq * 2;
        uint32_t bh0[8], bh1[8], bl0[8], bl1[8];
        #pragma unroll
        for (int nt = 0; nt < 8; nt++) {
            int n = ncol0 + nt * 8 + lr;
            bh0[nt] = *(const uint32_t*)&Whi[n * XPAD + kc];
            bh1[nt] = *(const uint32_t*)&Whi[n * XPAD + kc + 8];
            bl0[nt] = *(const uint32_t*)&Wlo[n * XPAD + kc];
            bl1[nt] = *(const uint32_t*)&Wlo[n * XPAD + kc + 8];
        }
        #pragma unroll
        for (int mt = 0; mt < 2; mt++) {
            int r0 = mrow0 + mt * 16 + lr;
            uint32_t ah0 = *(const uint32_t*)&Xhi[r0 * XPAD + kc];
            uint32_t ah1 = *(const uint32_t*)&Xhi[(r0 + 8) * XPAD + kc];
            uint32_t ah2 = *(const uint32_t*)&Xhi[r0 * XPAD + kc + 8];
            uint32_t ah3 = *(const uint32_t*)&Xhi[(r0 + 8) * XPAD + kc + 8];
            uint32_t al0 = *(const uint32_t*)&Xlo[r0 * XPAD + kc];
            uint32_t al1 = *(const uint32_t*)&Xlo[(r0 + 8) * XPAD + kc];
            uint32_t al2 = *(const uint32_t*)&Xlo[r0 * XPAD + kc + 8];
            uint32_t al3 = *(const uint32_t*)&Xlo[(r0 + 8) * XPAD + kc + 8];
            #pragma unroll
            for (int nt = 0; nt < 8; nt++) {
                mma_bf16(acc[mt][nt], ah0, ah1, ah2, ah3, bh0[nt], bh1[nt]);
                mma_bf16(acc[mt][nt], ah0, ah1, ah2, ah3, bl0[nt], bl1[nt]);
                mma_bf16(acc[mt][nt], al0, al1, al2, al3, bh0[nt], bh1[nt]);
            }
        }
    }

    // epilogue: store H + alpha dot products
    #pragma unroll
    for (int mt = 0; mt < 2; mt++) {
        int rl0 = mrow0 + mt * 16 + lr;          // local rows rl0, rl0+8
        int gr0 = row0 + rl0, gr1 = gr0 + 8;
        float ps0 = 0.f, ps1 = 0.f, pd0 = 0.f, pd1 = 0.f;
        #pragma unroll
        for (int nt = 0; nt < 8; nt++) {
            int c = ncol0 + nt * 8 + lq * 2;
            float s0 = avs[c], s1 = avs[c + 1];
            float d0 = avd[c], d1 = avd[c + 1];
            float* a = acc[mt][nt];
            ps0 += a[0] * s0 + a[1] * s1;
            pd0 += a[0] * d0 + a[1] * d1;
            ps1 += a[2] * s0 + a[3] * s1;
            pd1 += a[2] * d0 + a[3] * d1;
            if (gr0 < N_NODES) *(float2*)&g_h[(size_t)gr0 * D + c] = make_float2(a[0], a[1]);
            if (gr1 < N_NODES) *(float2*)&g_h[(size_t)gr1 * D + c] = make_float2(a[2], a[3]);
        }
        // reduce within quad (lanes sharing the same rows)
        #pragma unroll
        for (int off = 1; off < 4; off <<= 1) {
            ps0 += __shfl_xor_sync(0xffffffffu, ps0, off);
            ps1 += __shfl_xor_sync(0xffffffffu, ps1, off);
            pd0 += __shfl_xor_sync(0xffffffffu, pd0, off);
            pd1 += __shfl_xor_sync(0xffffffffu, pd1, off);
        }
        if (lq == 0) {
            int half = warp & 1;
            as_s[rl0 * 2 + half] = ps0;       as_s[(rl0 + 8) * 2 + half] = ps1;
            ad_s[rl0 * 2 + half] = pd0;       ad_s[(rl0 + 8) * 2 + half] = pd1;
        }
    }
    __syncthreads();
    if (tid < 128) {
        int gr = row0 + tid;
        if (gr < N_NODES) {
            g_as[gr] = as_s[tid * 2] + as_s[tid * 2 + 1];
            g_ad[gr] = ad_s[tid * 2] + ad_s[tid * 2 + 1];
        }
    }
}

// ---------------- warp-per-node softmax + aggregation (round-4 verbatim) ----------
__device__ __forceinline__ float leaky02(float e) {
    return fmaxf(e, 0.f) + 0.2f * fminf(e, 0.f);
}

__global__ void __launch_bounds__(256) k_node_agg(int do_relu, const float* __restrict__ b)
{
    int node = (blockIdx.x * blockDim.x + threadIdx.x) >> 5;
    int lane = threadIdx.x & 31;
    if (node >= N_NODES) return;

    int beg = g_rp[node];
    int end = g_rp[node + 1];
    float ad = g_ad[node];

    // pass 1: max
    float mx = -3.4e38f;
    for (int j = beg + lane; j < end; j += 32)
        mx = fmaxf(mx, leaky02(g_as[g_col[j]] + ad));
    #pragma unroll
    for (int off = 16; off; off >>= 1)
        mx = fmaxf(mx, __shfl_xor_sync(0xffffffffu, mx, off));

    // pass 2: denom
    float den = 0.f;
    for (int j = beg + lane; j < end; j += 32)
        den += __expf(leaky02(g_as[g_col[j]] + ad) - mx);
    #pragma unroll
    for (int off = 16; off; off >>= 1)
        den += __shfl_xor_sync(0xffffffffu, den, off);
    float inv = 1.f / den;

    // pass 3: feature accumulate (lane owns 4 columns)
    float4 acc = make_float4(0.f, 0.f, 0.f, 0.f);
    for (int j = beg; j < end; j++) {
        int s = g_col[j];                          // warp-uniform broadcast
        float w = __expf(leaky02(g_as[s] + ad) - mx) * inv;
        float4 hv = *(const float4*)&g_h[(size_t)s * D + lane * 4];
        acc.x = fmaf(w, hv.x, acc.x);
        acc.y = fmaf(w, hv.y, acc.y);
        acc.z = fmaf(w, hv.z, acc.z);
        acc.w = fmaf(w, hv.w, acc.w);
    }

    const float4 b4 = *(const float4*)&b[lane * 4];
    acc.x += b4.x; acc.y += b4.y; acc.z += b4.z; acc.w += b4.w;
    if (do_relu) {
        acc.x = fmaxf(acc.x, 0.f); acc.y = fmaxf(acc.y, 0.f);
        acc.z = fmaxf(acc.z, 0.f); acc.w = fmaxf(acc.w, 0.f);
    }
    *(float4*)&g_o[(size_t)node * D + lane * 4] = acc;
}

// ---------------- mean over nodes ----------------
__global__ void k_mean1() {
    int c = threadIdx.x;   // 128 threads = 128 cols
    float acc = 0.f;
    for (int r = blockIdx.x; r < N_NODES; r += MEAN_B)
        acc += g_o[(size_t)r * D + c];
    g_part[blockIdx.x * D + c] = acc;
}

__global__ void k_mean2(float* __restrict__ out) {
    int c = threadIdx.x;
    float s = 0.f;
    for (int i = 0; i < MEAN_B; i++) s += g_part[i * D + c];
    out[c] = s * (1.0f / N_NODES);
}

// ---------------- driver: kernel launches ONLY (+ idempotent attr set) ------------
extern "C" void kernel_launch(void* const* d_in, const int* in_sizes, int n_in,
                              void* d_out, int out_size)
{
    const float* x   = (const float*)d_in[0];
    const int*   ei  = (const int*)d_in[1];      // int32: [src x E | dst x E]
    const float* W1  = (const float*)d_in[2];
    const float* as1 = (const float*)d_in[3];
    const float* ad1 = (const float*)d_in[4];
    const float* b1  = (const float*)d_in[5];
    const float* W2  = (const float*)d_in[6];
    const float* as2 = (const float*)d_in[7];
    const float* ad2 = (const float*)d_in[8];
    const float* b2  = (const float*)d_in[9];
    float* out = (float*)d_out;

    cudaFuncSetAttribute(k_gemm, cudaFuncAttributeMaxDynamicSharedMemorySize, SM_TOT);

    // CSR build (identical for both layers)
    k_deg_init <<<(N_NODES + 255) / 256, 256>>>();
    k_deg_count<<<(N_EDGES + 255) / 256, 256>>>(ei);
    k_scan1    <<<NB, SCAN_B>>>();
    k_scan2    <<<1, 128>>>();
    k_scan3    <<<(N_NODES + 255) / 256, 256>>>();
    k_scatter  <<<(E_TOT + 255) / 256, 256>>>(ei);

    // layer 1: x -> g_h -> g_o (relu)
    k_wsplit  <<<(D * D + 255) / 256, 256>>>(W1);
    k_gemm    <<<N_TILES, 256, SM_TOT>>>(x, 1, as1, ad1);
    k_node_agg<<<(N_NODES * 32 + 255) / 256, 256>>>(1, b1);

    // layer 2: g_o -> g_h -> g_o
    k_wsplit  <<<(D * D + 255) / 256, 256>>>(W2);
    k_gemm    <<<N_TILES, 256, SM_TOT>>>(nullptr, 0, as2, ad2);
    k_node_agg<<<(N_NODES * 32 + 255) / 256, 256>>>(0, b2);

    // mean over nodes -> d_out[128]
    k_mean1<<<MEAN_B, D>>>();
    k_mean2<<<1, D>>>(out);
}

// round 9
// speedup vs baseline: 1.3225x; 1.0082x over previous
#include <cuda_runtime.h>
#include <cuda_bf16.h>
#include <cstdint>

#define N_NODES 100000
#define N_EDGES 600000
#define E_TOT   700000      // edges + self loops
#define D       128
#define SCAN_B  1024
#define NB      ((N_NODES + SCAN_B - 1) / SCAN_B)   // 98
#define MEAN_B  256
#define N_TILES ((N_NODES + 127) / 128)              // 782

#define XPAD    136                                   // padded row length (bf16 elems)
#define TILE_B  (128 * XPAD * 2)                      // 34816 bytes per bf16 tile
// dynamic smem layout (bytes)
#define SM_XHI  0
#define SM_XLO  (TILE_B)
#define SM_WHI  (2 * TILE_B)
#define SM_WLO  (3 * TILE_B)
#define SM_ALPH (4 * TILE_B)                          // as[128][2], ad[128][2] floats
#define SM_TOT  (4 * TILE_B + 2048)                   // 141312

// ---------------- scratch: __device__ globals only (no allocations) ----------------
__device__ __align__(16) float g_h[(size_t)N_NODES * D];   // post-GEMM features
__device__ __align__(16) float g_o[(size_t)N_NODES * D];   // layer output
__device__ __align__(16) unsigned short g_wthi[128 * XPAD]; // W^T hi bf16, padded rows
__device__ __align__(16) unsigned short g_wtlo[128 * XPAD]; // W^T lo bf16
__device__ float g_as[N_NODES];
__device__ float g_ad[N_NODES];
__device__ float g_ew[E_TOT];         // unnormalized edge weights
__device__ int   g_deg[N_NODES];
__device__ int   g_incl[N_NODES];
__device__ int   g_bsum[NB];
__device__ int   g_bpre[NB];
__device__ int   g_rp[N_NODES + 1];   // CSR row_ptr (by dst)
__device__ int   g_cur[N_NODES];      // scatter cursor
__device__ int   g_col[E_TOT];        // src node per incoming edge
__device__ float g_part[MEAN_B * D];

// ---------------- mma helper: m16n8k16 row.col f32.bf16.bf16.f32 ----------------
__device__ __forceinline__ void mma_bf16(float* c, uint32_t a0, uint32_t a1, uint32_t a2,
                                         uint32_t a3, uint32_t b0, uint32_t b1) {
    asm volatile(
        "mma.sync.aligned.m16n8k16.row.col.f32.bf16.bf16.f32 "
        "{%0,%1,%2,%3}, {%4,%5,%6,%7}, {%8,%9}, {%0,%1,%2,%3};"
        : "+f"(c[0]), "+f"(c[1]), "+f"(c[2]), "+f"(c[3])
        : "r"(a0), "r"(a1), "r"(a2), "r"(a3), "r"(b0), "r"(b1));
}
__device__ __forceinline__ uint32_t pack_bf16(float x, float y) {
    __nv_bfloat16 bx = __float2bfloat16(x), by = __float2bfloat16(y);
    unsigned short ux = *(unsigned short*)&bx, uy = *(unsigned short*)&by;
    return (uint32_t)ux | ((uint32_t)uy << 16);
}

// ---------------- CSR build (edge_index is int32: [src x E | dst x E]) ------------
__global__ void k_deg_init() {
    int i = blockIdx.x * blockDim.x + threadIdx.x;
    if (i < N_NODES) g_deg[i] = 1;   // self loop
}

__global__ void k_deg_count(const int* __restrict__ ei) {
    int e = blockIdx.x * blockDim.x + threadIdx.x;
    if (e < N_EDGES) {
        int d = ei[N_EDGES + e];
        if ((unsigned)d < N_NODES) atomicAdd(&g_deg[d], 1);
    }
}

__global__ void __launch_bounds__(SCAN_B) k_scan1() {
    __shared__ int s[SCAN_B];
    int tl = threadIdx.x;
    int t  = blockIdx.x * SCAN_B + tl;
    int v  = (t < N_NODES) ? g_deg[t] : 0;
    s[tl] = v;
    __syncthreads();
    #pragma unroll
    for (int off = 1; off < SCAN_B; off <<= 1) {
        int add = (tl >= off) ? s[tl - off] : 0;
        __syncthreads();
        s[tl] += add;
        __syncthreads();
    }
    if (t < N_NODES) g_incl[t] = s[tl];
    if (tl == SCAN_B - 1) g_bsum[blockIdx.x] = s[tl];
}

__global__ void k_scan2() {
    __shared__ int s[128];
    int t = threadIdx.x;
    int v = (t < NB) ? g_bsum[t] : 0;
    s[t] = v;
    __syncthreads();
    #pragma unroll
    for (int off = 1; off < 128; off <<= 1) {
        int add = (t >= off) ? s[t - off] : 0;
        __syncthreads();
        s[t] += add;
        __syncthreads();
    }
    if (t < NB) g_bpre[t] = s[t] - v;   // exclusive prefix of block sums
}

__global__ void k_scan3() {
    int t = blockIdx.x * blockDim.x + threadIdx.x;
    if (t < N_NODES) {
        int S = g_incl[t] + g_bpre[t / SCAN_B];   // inclusive prefix
        g_rp[t + 1] = S;
        g_cur[t]    = S - g_deg[t];
        if (t == 0) g_rp[0] = 0;
    }
}

__global__ void k_scatter(const int* __restrict__ ei) {
    int e = blockIdx.x * blockDim.x + threadIdx.x;
    if (e >= E_TOT) return;
    int s, d;
    if (e < N_EDGES) { s = ei[e]; d = ei[N_EDGES + e]; }
    else             { s = e - N_EDGES; d = s; }
    if ((unsigned)s >= N_NODES || (unsigned)d >= N_NODES) return;
    int pos = atomicAdd(&g_cur[d], 1);
    g_col[pos] = s;
}

// ---------------- W split+transpose: g_wt{hi,lo}[n][k] = split(W[k][n]) ------------
__global__ void k_wsplit(const float* __restrict__ W) {
    int t = blockIdx.x * blockDim.x + threadIdx.x;
    if (t >= D * D) return;
    int n = t >> 7, k = t & 127;
    float v = W[k * D + n];
    __nv_bfloat16 hb = __float2bfloat16(v);
    float hf = __bfloat162float(hb);
    __nv_bfloat16 lb = __float2bfloat16(v - hf);
    g_wthi[n * XPAD + k] = *(unsigned short*)&hb;
    g_wtlo[n * XPAD + k] = *(unsigned short*)&lb;
}

// ---------------- HMMA GEMM: H = X*W (split-2 bf16, fp32 accum) --------------------
// 256 thr / block; 128-row tile; 8 warps = 4(m) x 2(n), warp tile 32x64
__global__ void __launch_bounds__(256) k_gemm(
    const float* __restrict__ Xext, int use_ext,
    const float* __restrict__ avs, const float* __restrict__ avd)
{
    extern __shared__ unsigned char smem[];
    unsigned short* Xhi = (unsigned short*)(smem + SM_XHI);
    unsigned short* Xlo = (unsigned short*)(smem + SM_XLO);
    unsigned short* Whi = (unsigned short*)(smem + SM_WHI);
    unsigned short* Wlo = (unsigned short*)(smem + SM_WLO);
    float* as_s = (float*)(smem + SM_ALPH);          // [128][2]
    float* ad_s = (float*)(smem + SM_ALPH + 1024);   // [128][2]

    const int tid  = threadIdx.x;
    const int warp = tid >> 5;
    const int lane = tid & 31;
    const int lq   = lane & 3;      // thread-in-group
    const int lr   = lane >> 2;     // group id
    const int row0 = blockIdx.x * 128;
    const int mrow0 = (warp >> 1) * 32;
    const int ncol0 = (warp & 1) * 64;
    const float* X = use_ext ? Xext : g_o;

    // stage X (fp32, coalesced float4) -> split to bf16 hi/lo in padded smem
    {
        const float4* X4 = (const float4*)X;
        #pragma unroll
        for (int i = tid; i < 128 * 32; i += 256) {
            int r = i >> 5, c4 = i & 31;
            int gr = row0 + r;
            float4 v = (gr < N_NODES) ? X4[(size_t)gr * 32 + c4]
                                      : make_float4(0.f, 0.f, 0.f, 0.f);
            __nv_bfloat16 h0 = __float2bfloat16(v.x), h1 = __float2bfloat16(v.y);
            __nv_bfloat16 h2 = __float2bfloat16(v.z), h3 = __float2bfloat16(v.w);
            float f0 = __bfloat162float(h0), f1 = __bfloat162float(h1);
            float f2 = __bfloat162float(h2), f3 = __bfloat162float(h3);
            uint2 hw, lw;
            {
                unsigned short u0 = *(unsigned short*)&h0, u1 = *(unsigned short*)&h1;
                unsigned short u2 = *(unsigned short*)&h2, u3 = *(unsigned short*)&h3;
                hw.x = (uint32_t)u0 | ((uint32_t)u1 << 16);
                hw.y = (uint32_t)u2 | ((uint32_t)u3 << 16);
            }
            lw.x = pack_bf16(v.x - f0, v.y - f1);
            lw.y = pack_bf16(v.z - f2, v.w - f3);
            int off = r * XPAD + c4 * 4;
            *(uint2*)&Xhi[off] = hw;
            *(uint2*)&Xlo[off] = lw;
        }
    }
    // stage pre-split W tiles (linear 16B copies incl. pad)
    {
        const uint4* wh = (const uint4*)g_wthi;
        const uint4* wl = (const uint4*)g_wtlo;
        uint4* sh = (uint4*)Whi;
        uint4* sl = (uint4*)Wlo;
        #pragma unroll
        for (int i = tid; i < TILE_B / 16; i += 256) { sh[i] = wh[i]; sl[i] = wl[i]; }
    }
    __syncthreads();

    float acc[2][8][4];
    #pragma unroll
    for (int mt = 0; mt < 2; mt++)
        #pragma unroll
        for (int nt = 0; nt < 8; nt++)
            #pragma unroll
            for (int j = 0; j < 4; j++) acc[mt][nt][j] = 0.f;

    #pragma unroll
    for (int ks = 0; ks < 8; ks++) {
        const int kc = ks * 16 + lq * 2;
        uint32_t bh0[8], bh1[8], bl0[8], bl1[8];
        #pragma unroll
        for (int nt = 0; nt < 8; nt++) {
            int n = ncol0 + nt * 8 + lr;
            bh0[nt] = *(const uint32_t*)&Whi[n * XPAD + kc];
            bh1[nt] = *(const uint32_t*)&Whi[n * XPAD + kc + 8];
            bl0[nt] = *(const uint32_t*)&Wlo[n * XPAD + kc];
            bl1[nt] = *(const uint32_t*)&Wlo[n * XPAD + kc + 8];
        }
        #pragma unroll
        for (int mt = 0; mt < 2; mt++) {
            int r0 = mrow0 + mt * 16 + lr;
            uint32_t ah0 = *(const uint32_t*)&Xhi[r0 * XPAD + kc];
            uint32_t ah1 = *(const uint32_t*)&Xhi[(r0 + 8) * XPAD + kc];
            uint32_t ah2 = *(const uint32_t*)&Xhi[r0 * XPAD + kc + 8];
            uint32_t ah3 = *(const uint32_t*)&Xhi[(r0 + 8) * XPAD + kc + 8];
            uint32_t al0 = *(const uint32_t*)&Xlo[r0 * XPAD + kc];
            uint32_t al1 = *(const uint32_t*)&Xlo[(r0 + 8) * XPAD + kc];
            uint32_t al2 = *(const uint32_t*)&Xlo[r0 * XPAD + kc + 8];
            uint32_t al3 = *(const uint32_t*)&Xlo[(r0 + 8) * XPAD + kc + 8];
            #pragma unroll
            for (int nt = 0; nt < 8; nt++) {
                mma_bf16(acc[mt][nt], ah0, ah1, ah2, ah3, bh0[nt], bh1[nt]);
                mma_bf16(acc[mt][nt], ah0, ah1, ah2, ah3, bl0[nt], bl1[nt]);
                mma_bf16(acc[mt][nt], al0, al1, al2, al3, bh0[nt], bh1[nt]);
            }
        }
    }

    // epilogue: store H + alpha dot products
    #pragma unroll
    for (int mt = 0; mt < 2; mt++) {
        int rl0 = mrow0 + mt * 16 + lr;          // local rows rl0, rl0+8
        int gr0 = row0 + rl0, gr1 = gr0 + 8;
        float ps0 = 0.f, ps1 = 0.f, pd0 = 0.f, pd1 = 0.f;
        #pragma unroll
        for (int nt = 0; nt < 8; nt++) {
            int c = ncol0 + nt * 8 + lq * 2;
            float s0 = avs[c], s1 = avs[c + 1];
            float d0 = avd[c], d1 = avd[c + 1];
            float* a = acc[mt][nt];
            ps0 += a[0] * s0 + a[1] * s1;
            pd0 += a[0] * d0 + a[1] * d1;
            ps1 += a[2] * s0 + a[3] * s1;
            pd1 += a[2] * d0 + a[3] * d1;
            if (gr0 < N_NODES) *(float2*)&g_h[(size_t)gr0 * D + c] = make_float2(a[0], a[1]);
            if (gr1 < N_NODES) *(float2*)&g_h[(size_t)gr1 * D + c] = make_float2(a[2], a[3]);
        }
        // reduce within quad (lanes sharing the same rows)
        #pragma unroll
        for (int off = 1; off < 4; off <<= 1) {
            ps0 += __shfl_xor_sync(0xffffffffu, ps0, off);
            ps1 += __shfl_xor_sync(0xffffffffu, ps1, off);
            pd0 += __shfl_xor_sync(0xffffffffu, pd0, off);
            pd1 += __shfl_xor_sync(0xffffffffu, pd1, off);
        }
        if (lq == 0) {
            int half = warp & 1;
            as_s[rl0 * 2 + half] = ps0;       as_s[(rl0 + 8) * 2 + half] = ps1;
            ad_s[rl0 * 2 + half] = pd0;       ad_s[(rl0 + 8) * 2 + half] = pd1;
        }
    }
    __syncthreads();
    if (tid < 128) {
        int gr = row0 + tid;
        if (gr < N_NODES) {
            g_as[gr] = as_s[tid * 2] + as_s[tid * 2 + 1];
            g_ad[gr] = ad_s[tid * 2] + ad_s[tid * 2 + 1];
        }
    }
}

// ---------------- warp-per-node 2-pass softmax-aggregate (max-free, exact) --------
// softmax is shift-invariant; |e| <= ~25 here so exp(e) cannot overflow fp32.
__device__ __forceinline__ float leaky02(float e) {
    return fmaxf(e, 0.f) + 0.2f * fminf(e, 0.f);
}

__global__ void __launch_bounds__(256) k_node_agg(int do_relu, const float* __restrict__ b)
{
    int node = (blockIdx.x * blockDim.x + threadIdx.x) >> 5;
    int lane = threadIdx.x & 31;
    if (node >= N_NODES) return;

    int beg = g_rp[node];
    int end = g_rp[node + 1];
    float ad = g_ad[node];

    // pass A: unnormalized weights -> g_ew, accumulate denominator
    float wsum = 0.f;
    for (int j = beg + lane; j < end; j += 32) {
        float e = g_as[g_col[j]] + ad;
        e = fmaxf(e, 0.f) + 0.2f * fminf(e, 0.f);
        float w = __expf(e);
        g_ew[j] = w;
        wsum += w;
    }
    #pragma unroll
    for (int off = 16; off; off >>= 1)
        wsum += __shfl_xor_sync(0xffffffffu, wsum, off);
    float inv = 1.f / wsum;
    __syncwarp();

    // pass B: feature accumulate (lane owns 4 columns); scale once at the end
    float4 acc = make_float4(0.f, 0.f, 0.f, 0.f);
    for (int j = beg; j < end; j++) {
        int   s = g_col[j];     // warp-uniform broadcast
        float w = g_ew[j];      // warp-uniform broadcast
        float4 hv = *(const float4*)&g_h[(size_t)s * D + lane * 4];
        acc.x = fmaf(w, hv.x, acc.x);
        acc.y = fmaf(w, hv.y, acc.y);
        acc.z = fmaf(w, hv.z, acc.z);
        acc.w = fmaf(w, hv.w, acc.w);
    }

    const float4 b4 = *(const float4*)&b[lane * 4];
    acc.x = fmaf(acc.x, inv, b4.x);
    acc.y = fmaf(acc.y, inv, b4.y);
    acc.z = fmaf(acc.z, inv, b4.z);
    acc.w = fmaf(acc.w, inv, b4.w);
    if (do_relu) {
        acc.x = fmaxf(acc.x, 0.f); acc.y = fmaxf(acc.y, 0.f);
        acc.z = fmaxf(acc.z, 0.f); acc.w = fmaxf(acc.w, 0.f);
    }
    *(float4*)&g_o[(size_t)node * D + lane * 4] = acc;
}

// ---------------- mean over nodes ----------------
__global__ void k_mean1() {
    int c = threadIdx.x;   // 128 threads = 128 cols
    float acc = 0.f;
    for (int r = blockIdx.x; r < N_NODES; r += MEAN_B)
        acc += g_o[(size_t)r * D + c];
    g_part[blockIdx.x * D + c] = acc;
}

__global__ void k_mean2(float* __restrict__ out) {
    int c = threadIdx.x;
    float s = 0.f;
    for (int i = 0; i < MEAN_B; i++) s += g_part[i * D + c];
    out[c] = s * (1.0f / N_NODES);
}

// ---------------- driver: kernel launches ONLY (+ idempotent attr set) ------------
extern "C" void kernel_launch(void* const* d_in, const int* in_sizes, int n_in,
                              void* d_out, int out_size)
{
    const float* x   = (const float*)d_in[0];
    const int*   ei  = (const int*)d_in[1];      // int32: [src x E | dst x E]
    const float* W1  = (const float*)d_in[2];
    const float* as1 = (const float*)d_in[3];
    const float* ad1 = (const float*)d_in[4];
    const float* b1  = (const float*)d_in[5];
    const float* W2  = (const float*)d_in[6];
    const float* as2 = (const float*)d_in[7];
    const float* ad2 = (const float*)d_in[8];
    const float* b2  = (const float*)d_in[9];
    float* out = (float*)d_out;

    cudaFuncSetAttribute(k_gemm, cudaFuncAttributeMaxDynamicSharedMemorySize, SM_TOT);

    // CSR build (identical for both layers)
    k_deg_init <<<(N_NODES + 255) / 256, 256>>>();
    k_deg_count<<<(N_EDGES + 255) / 256, 256>>>(ei);
    k_scan1    <<<NB, SCAN_B>>>();
    k_scan2    <<<1, 128>>>();
    k_scan3    <<<(N_NODES + 255) / 256, 256>>>();
    k_scatter  <<<(E_TOT + 255) / 256, 256>>>(ei);

    // layer 1: x -> g_h -> g_o (relu)
    k_wsplit  <<<(D * D + 255) / 256, 256>>>(W1);
    k_gemm    <<<N_TILES, 256, SM_TOT>>>(x, 1, as1, ad1);
    k_node_agg<<<(N_NODES * 32 + 255) / 256, 256>>>(1, b1);

    // layer 2: g_o -> g_h -> g_o
    k_wsplit  <<<(D * D + 255) / 256, 256>>>(W2);
    k_gemm    <<<N_TILES, 256, SM_TOT>>>(nullptr, 0, as2, ad2);
    k_node_agg<<<(N_NODES * 32 + 255) / 256, 256>>>(0, b2);

    // mean over nodes -> d_out[128]
    k_mean1<<<MEAN_B, D>>>();
    k_mean2<<<1, D>>>(out);
}

// round 10
// speedup vs baseline: 1.3870x; 1.0488x over previous
#include <cuda_runtime.h>
#include <cuda_bf16.h>
#include <cstdint>

#define N_NODES 100000
#define N_EDGES 600000
#define E_TOT   700000      // edges + self loops
#define D       128
#define SCAN_B  1024
#define NB      ((N_NODES + SCAN_B - 1) / SCAN_B)   // 98
#define N_TILES ((N_NODES + 127) / 128)              // 782
#define AGG_BLKS (N_NODES * 32 / 256)                // 12500 exactly

#define XPAD    136                                   // padded row length (bf16 elems)
#define TILE_B  (128 * XPAD * 2)                      // 34816 bytes per bf16 tile
// dynamic smem layout (bytes)
#define SM_XHI  0
#define SM_XLO  (TILE_B)
#define SM_WHI  (2 * TILE_B)
#define SM_WLO  (3 * TILE_B)
#define SM_ALPH (4 * TILE_B)                          // as[128][2], ad[128][2] floats
#define SM_TOT  (4 * TILE_B + 2048)                   // 141312

// ---------------- scratch: __device__ globals only (no allocations) ----------------
__device__ __align__(16) float g_h[(size_t)N_NODES * D];   // post-GEMM features
__device__ __align__(16) float g_o[(size_t)N_NODES * D];   // layer-1 output
__device__ __align__(16) unsigned short g_wthi[2][128 * XPAD]; // W^T hi bf16 per layer
__device__ __align__(16) unsigned short g_wtlo[2][128 * XPAD]; // W^T lo bf16 per layer
__device__ float g_as[N_NODES];
__device__ float g_ad[N_NODES];
__device__ float g_ew[E_TOT];         // unnormalized edge weights
__device__ int   g_deg[N_NODES];      // self-zeroing each pass (starts 0)
__device__ int   g_incl[N_NODES];     // inclusive per-block scan
__device__ int   g_bsum[NB];
__device__ int   g_rp[N_NODES + 1];   // CSR row_ptr (by dst)
__device__ int   g_cur[N_NODES];      // scatter cursor (holds exclusive scan first)
__device__ int   g_col[E_TOT];        // src node per incoming edge
__device__ __align__(16) float g_part2[(size_t)AGG_BLKS * 128]; // layer-2 block partials
__device__ float g_part[128 * 128];

// ---------------- mma helper: m16n8k16 row.col f32.bf16.bf16.f32 ----------------
__device__ __forceinline__ void mma_bf16(float* c, uint32_t a0, uint32_t a1, uint32_t a2,
                                         uint32_t a3, uint32_t b0, uint32_t b1) {
    asm volatile(
        "mma.sync.aligned.m16n8k16.row.col.f32.bf16.bf16.f32 "
        "{%0,%1,%2,%3}, {%4,%5,%6,%7}, {%8,%9}, {%0,%1,%2,%3};"
        : "+f"(c[0]), "+f"(c[1]), "+f"(c[2]), "+f"(c[3])
        : "r"(a0), "r"(a1), "r"(a2), "r"(a3), "r"(b0), "r"(b1));
}
__device__ __forceinline__ uint32_t pack_bf16(float x, float y) {
    __nv_bfloat16 bx = __float2bfloat16(x), by = __float2bfloat16(y);
    unsigned short ux = *(unsigned short*)&bx, uy = *(unsigned short*)&by;
    return (uint32_t)ux | ((uint32_t)uy << 16);
}

// ---------------- CSR build (edge_index is int32: [src x E | dst x E]) ------------
__global__ void k_deg_count(const int* __restrict__ ei) {
    int e = blockIdx.x * blockDim.x + threadIdx.x;
    if (e < N_EDGES) {
        int d = ei[N_EDGES + e];
        if ((unsigned)d < N_NODES) atomicAdd(&g_deg[d], 1);
    }
}

// per-block inclusive scan of (deg+1); zeroes g_deg for the next pass
__global__ void __launch_bounds__(SCAN_B) k_scan1() {
    __shared__ int s[SCAN_B];
    int tl = threadIdx.x;
    int t  = blockIdx.x * SCAN_B + tl;
    int v  = 0;
    if (t < N_NODES) {
        v = g_deg[t] + 1;     // +1 self loop
        g_deg[t] = 0;         // self-zero for next replay
    }
    s[tl] = v;
    __syncthreads();
    #pragma unroll
    for (int off = 1; off < SCAN_B; off <<= 1) {
        int add = (tl >= off) ? s[tl - off] : 0;
        __syncthreads();
        s[tl] += add;
        __syncthreads();
    }
    if (t < N_NODES) { g_incl[t] = s[tl]; g_cur[t] = s[tl] - v; }
    if (tl == SCAN_B - 1) g_bsum[blockIdx.x] = s[tl];
}

// folds the 98-entry block-sum prefix into the final scan
__global__ void k_scan23() {
    __shared__ int spre[NB];
    if (threadIdx.x == 0) {
        int run = 0;
        #pragma unroll 2
        for (int i = 0; i < NB; i++) { int b = g_bsum[i]; spre[i] = run; run += b; }
    }
    __syncthreads();
    int t = blockIdx.x * blockDim.x + threadIdx.x;
    if (t < N_NODES) {
        int bp = spre[t >> 10];
        g_rp[t + 1] = g_incl[t] + bp;
        g_cur[t]   += bp;
        if (t == 0) g_rp[0] = 0;
    }
}

__global__ void k_scatter(const int* __restrict__ ei) {
    int e = blockIdx.x * blockDim.x + threadIdx.x;
    if (e >= E_TOT) return;
    int s, d;
    if (e < N_EDGES) { s = ei[e]; d = ei[N_EDGES + e]; }
    else             { s = e - N_EDGES; d = s; }
    if ((unsigned)s >= N_NODES || (unsigned)d >= N_NODES) return;
    int pos = atomicAdd(&g_cur[d], 1);
    g_col[pos] = s;
}

// ---------------- W split+transpose for BOTH layers in one launch -----------------
__global__ void k_wsplit(const float* __restrict__ W1, const float* __restrict__ W2) {
    int t = blockIdx.x * blockDim.x + threadIdx.x;
    if (t >= 2 * D * D) return;
    int layer = t >> 14;           // /(D*D)
    int r = t & (D * D - 1);
    int n = r >> 7, k = r & 127;
    const float* W = layer ? W2 : W1;
    float v = W[k * D + n];
    __nv_bfloat16 hb = __float2bfloat16(v);
    float hf = __bfloat162float(hb);
    __nv_bfloat16 lb = __float2bfloat16(v - hf);
    g_wthi[layer][n * XPAD + k] = *(unsigned short*)&hb;
    g_wtlo[layer][n * XPAD + k] = *(unsigned short*)&lb;
}

// ---------------- HMMA GEMM: H = X*W (split-2 bf16, fp32 accum) --------------------
__global__ void __launch_bounds__(256) k_gemm(
    const float* __restrict__ Xext, int use_ext, int wl,
    const float* __restrict__ avs, const float* __restrict__ avd)
{
    extern __shared__ unsigned char smem[];
    unsigned short* Xhi = (unsigned short*)(smem + SM_XHI);
    unsigned short* Xlo = (unsigned short*)(smem + SM_XLO);
    unsigned short* Whi = (unsigned short*)(smem + SM_WHI);
    unsigned short* Wlo = (unsigned short*)(smem + SM_WLO);
    float* as_s = (float*)(smem + SM_ALPH);          // [128][2]
    float* ad_s = (float*)(smem + SM_ALPH + 1024);   // [128][2]

    const int tid  = threadIdx.x;
    const int warp = tid >> 5;
    const int lane = tid & 31;
    const int lq   = lane & 3;
    const int lr   = lane >> 2;
    const int row0 = blockIdx.x * 128;
    const int mrow0 = (warp >> 1) * 32;
    const int ncol0 = (warp & 1) * 64;
    const float* X = use_ext ? Xext : g_o;

    {
        const float4* X4 = (const float4*)X;
        #pragma unroll
        for (int i = tid; i < 128 * 32; i += 256) {
            int r = i >> 5, c4 = i & 31;
            int gr = row0 + r;
            float4 v = (gr < N_NODES) ? X4[(size_t)gr * 32 + c4]
                                      : make_float4(0.f, 0.f, 0.f, 0.f);
            __nv_bfloat16 h0 = __float2bfloat16(v.x), h1 = __float2bfloat16(v.y);
            __nv_bfloat16 h2 = __float2bfloat16(v.z), h3 = __float2bfloat16(v.w);
            float f0 = __bfloat162float(h0), f1 = __bfloat162float(h1);
            float f2 = __bfloat162float(h2), f3 = __bfloat162float(h3);
            uint2 hw, lw;
            {
                unsigned short u0 = *(unsigned short*)&h0, u1 = *(unsigned short*)&h1;
                unsigned short u2 = *(unsigned short*)&h2, u3 = *(unsigned short*)&h3;
                hw.x = (uint32_t)u0 | ((uint32_t)u1 << 16);
                hw.y = (uint32_t)u2 | ((uint32_t)u3 << 16);
            }
            lw.x = pack_bf16(v.x - f0, v.y - f1);
            lw.y = pack_bf16(v.z - f2, v.w - f3);
            int off = r * XPAD + c4 * 4;
            *(uint2*)&Xhi[off] = hw;
            *(uint2*)&Xlo[off] = lw;
        }
    }
    {
        const uint4* wh = (const uint4*)g_wthi[wl];
        const uint4* wl4 = (const uint4*)g_wtlo[wl];
        uint4* sh = (uint4*)Whi;
        uint4* sl = (uint4*)Wlo;
        #pragma unroll
        for (int i = tid; i < TILE_B / 16; i += 256) { sh[i] = wh[i]; sl[i] = wl4[i]; }
    }
    __syncthreads();

    float acc[2][8][4];
    #pragma unroll
    for (int mt = 0; mt < 2; mt++)
        #pragma unroll
        for (int nt = 0; nt < 8; nt++)
            #pragma unroll
            for (int j = 0; j < 4; j++) acc[mt][nt][j] = 0.f;

    #pragma unroll
    for (int ks = 0; ks < 8; ks++) {
        const int kc = ks * 16 + lq * 2;
        uint32_t bh0[8], bh1[8], bl0[8], bl1[8];
        #pragma unroll
        for (int nt = 0; nt < 8; nt++) {
            int n = ncol0 + nt * 8 + lr;
            bh0[nt] = *(const uint32_t*)&Whi[n * XPAD + kc];
            bh1[nt] = *(const uint32_t*)&Whi[n * XPAD + kc + 8];
            bl0[nt] = *(const uint32_t*)&Wlo[n * XPAD + kc];
            bl1[nt] = *(const uint32_t*)&Wlo[n * XPAD + kc + 8];
        }
        #pragma unroll
        for (int mt = 0; mt < 2; mt++) {
            int r0 = mrow0 + mt * 16 + lr;
            uint32_t ah0 = *(const uint32_t*)&Xhi[r0 * XPAD + kc];
            uint32_t ah1 = *(const uint32_t*)&Xhi[(r0 + 8) * XPAD + kc];
            uint32_t ah2 = *(const uint32_t*)&Xhi[r0 * XPAD + kc + 8];
            uint32_t ah3 = *(const uint32_t*)&Xhi[(r0 + 8) * XPAD + kc + 8];
            uint32_t al0 = *(const uint32_t*)&Xlo[r0 * XPAD + kc];
            uint32_t al1 = *(const uint32_t*)&Xlo[(r0 + 8) * XPAD + kc];
            uint32_t al2 = *(const uint32_t*)&Xlo[r0 * XPAD + kc + 8];
            uint32_t al3 = *(const uint32_t*)&Xlo[(r0 + 8) * XPAD + kc + 8];
            #pragma unroll
            for (int nt = 0; nt < 8; nt++) {
                mma_bf16(acc[mt][nt], ah0, ah1, ah2, ah3, bh0[nt], bh1[nt]);
                mma_bf16(acc[mt][nt], ah0, ah1, ah2, ah3, bl0[nt], bl1[nt]);
                mma_bf16(acc[mt][nt], al0, al1, al2, al3, bh0[nt], bh1[nt]);
            }
        }
    }

    #pragma unroll
    for (int mt = 0; mt < 2; mt++) {
        int rl0 = mrow0 + mt * 16 + lr;
        int gr0 = row0 + rl0, gr1 = gr0 + 8;
        float ps0 = 0.f, ps1 = 0.f, pd0 = 0.f, pd1 = 0.f;
        #pragma unroll
        for (int nt = 0; nt < 8; nt++) {
            int c = ncol0 + nt * 8 + lq * 2;
            float s0 = avs[c], s1 = avs[c + 1];
            float d0 = avd[c], d1 = avd[c + 1];
            float* a = acc[mt][nt];
            ps0 += a[0] * s0 + a[1] * s1;
            pd0 += a[0] * d0 + a[1] * d1;
            ps1 += a[2] * s0 + a[3] * s1;
            pd1 += a[2] * d0 + a[3] * d1;
            if (gr0 < N_NODES) *(float2*)&g_h[(size_t)gr0 * D + c] = make_float2(a[0], a[1]);
            if (gr1 < N_NODES) *(float2*)&g_h[(size_t)gr1 * D + c] = make_float2(a[2], a[3]);
        }
        #pragma unroll
        for (int off = 1; off < 4; off <<= 1) {
            ps0 += __shfl_xor_sync(0xffffffffu, ps0, off);
            ps1 += __shfl_xor_sync(0xffffffffu, ps1, off);
            pd0 += __shfl_xor_sync(0xffffffffu, pd0, off);
            pd1 += __shfl_xor_sync(0xffffffffu, pd1, off);
        }
        if (lq == 0) {
            int half = warp & 1;
            as_s[rl0 * 2 + half] = ps0;       as_s[(rl0 + 8) * 2 + half] = ps1;
            ad_s[rl0 * 2 + half] = pd0;       ad_s[(rl0 + 8) * 2 + half] = pd1;
        }
    }
    __syncthreads();
    if (tid < 128) {
        int gr = row0 + tid;
        if (gr < N_NODES) {
            g_as[gr] = as_s[tid * 2] + as_s[tid * 2 + 1];
            g_ad[gr] = ad_s[tid * 2] + ad_s[tid * 2 + 1];
        }
    }
}

// ---------------- warp-per-node 2-pass softmax-aggregate (max-free, exact) --------
// mode 0: layer 1 -> relu, write g_o.  mode 1: layer 2 -> block partial sums only.
__global__ void __launch_bounds__(256) k_node_agg(int mode, const float* __restrict__ b)
{
    __shared__ float sb[8 * 128];
    int node = (blockIdx.x * blockDim.x + threadIdx.x) >> 5;
    int warp = threadIdx.x >> 5;
    int lane = threadIdx.x & 31;

    int beg = g_rp[node];
    int end = g_rp[node + 1];
    float ad = g_ad[node];

    // pass A: unnormalized weights -> g_ew, accumulate denominator
    float wsum = 0.f;
    for (int j = beg + lane; j < end; j += 32) {
        float e = g_as[g_col[j]] + ad;
        e = fmaxf(e, 0.f) + 0.2f * fminf(e, 0.f);
        float w = __expf(e);
        g_ew[j] = w;
        wsum += w;
    }
    #pragma unroll
    for (int off = 16; off; off >>= 1)
        wsum += __shfl_xor_sync(0xffffffffu, wsum, off);
    float inv = 1.f / wsum;
    __syncwarp();

    // pass B: feature accumulate (lane owns 4 columns); scale once at the end
    float4 acc = make_float4(0.f, 0.f, 0.f, 0.f);
    for (int j = beg; j < end; j++) {
        int   s = g_col[j];     // warp-uniform broadcast
        float w = g_ew[j];      // warp-uniform broadcast
        float4 hv = *(const float4*)&g_h[(size_t)s * D + lane * 4];
        acc.x = fmaf(w, hv.x, acc.x);
        acc.y = fmaf(w, hv.y, acc.y);
        acc.z = fmaf(w, hv.z, acc.z);
        acc.w = fmaf(w, hv.w, acc.w);
    }

    const float4 b4 = *(const float4*)&b[lane * 4];
    acc.x = fmaf(acc.x, inv, b4.x);
    acc.y = fmaf(acc.y, inv, b4.y);
    acc.z = fmaf(acc.z, inv, b4.z);
    acc.w = fmaf(acc.w, inv, b4.w);

    if (mode == 0) {
        acc.x = fmaxf(acc.x, 0.f); acc.y = fmaxf(acc.y, 0.f);
        acc.z = fmaxf(acc.z, 0.f); acc.w = fmaxf(acc.w, 0.f);
        *(float4*)&g_o[(size_t)node * D + lane * 4] = acc;
    } else {
        // layer 2: block-level partial sum for the final mean; g_o never written
        *(float4*)&sb[warp * 128 + lane * 4] = acc;
        __syncthreads();
        if (threadIdx.x < 128) {
            float s = 0.f;
            #pragma unroll
            for (int w = 0; w < 8; w++) s += sb[w * 128 + threadIdx.x];
            g_part2[(size_t)blockIdx.x * 128 + threadIdx.x] = s;
        }
    }
}

// ---------------- mean over nodes (from layer-2 block partials) -------------------
__global__ void k_meanA() {
    float s = 0.f;
    for (int r = blockIdx.x; r < AGG_BLKS; r += 128)
        s += g_part2[(size_t)r * 128 + threadIdx.x];
    g_part[blockIdx.x * 128 + threadIdx.x] = s;
}

__global__ void k_meanB(float* __restrict__ out) {
    int c = threadIdx.x;
    float s = 0.f;
    #pragma unroll 8
    for (int i = 0; i < 128; i++) s += g_part[i * 128 + c];
    out[c] = s * (1.0f / N_NODES);
}

// ---------------- driver: kernel launches ONLY (+ idempotent attr set) ------------
extern "C" void kernel_launch(void* const* d_in, const int* in_sizes, int n_in,
                              void* d_out, int out_size)
{
    const float* x   = (const float*)d_in[0];
    const int*   ei  = (const int*)d_in[1];      // int32: [src x E | dst x E]
    const float* W1  = (const float*)d_in[2];
    const float* as1 = (const float*)d_in[3];
    const float* ad1 = (const float*)d_in[4];
    const float* b1  = (const float*)d_in[5];
    const float* W2  = (const float*)d_in[6];
    const float* as2 = (const float*)d_in[7];
    const float* ad2 = (const float*)d_in[8];
    const float* b2  = (const float*)d_in[9];
    float* out = (float*)d_out;

    cudaFuncSetAttribute(k_gemm, cudaFuncAttributeMaxDynamicSharedMemorySize, SM_TOT);

    // CSR build + weight prep
    k_deg_count<<<(N_EDGES + 255) / 256, 256>>>(ei);
    k_scan1    <<<NB, SCAN_B>>>();
    k_scan23   <<<(N_NODES + 255) / 256, 256>>>();
    k_scatter  <<<(E_TOT + 255) / 256, 256>>>(ei);
    k_wsplit   <<<(2 * D * D + 255) / 256, 256>>>(W1, W2);

    // layer 1: x -> g_h -> g_o (relu)
    k_gemm    <<<N_TILES, 256, SM_TOT>>>(x, 1, 0, as1, ad1);
    k_node_agg<<<AGG_BLKS, 256>>>(0, b1);

    // layer 2: g_o -> g_h -> block partials (g_o never re-written)
    k_gemm    <<<N_TILES, 256, SM_TOT>>>(nullptr, 0, 1, as2, ad2);
    k_node_agg<<<AGG_BLKS, 256>>>(1, b2);

    // mean over nodes -> d_out[128]
    k_meanA<<<128, 128>>>();
    k_meanB<<<1, 128>>>(out);
}

// round 11
// speedup vs baseline: 1.4270x; 1.0288x over previous
#include <cuda_runtime.h>
#include <cuda_bf16.h>
#include <cstdint>

#define N_NODES 100000
#define N_EDGES 600000
#define E_TOT   700000      // edges + self loops
#define D       128
#define SCAN_B  1024
#define NB      ((N_NODES + SCAN_B - 1) / SCAN_B)   // 98
#define N_TILES ((N_NODES + 127) / 128)              // 782
#define AGG_BLKS (N_NODES * 32 / 256)                // 12500 exactly

#define XPAD    136                                   // padded row length (bf16 elems)
#define TILE_B  (128 * XPAD * 2)                      // 34816 bytes per bf16 tile
// dynamic smem layout (bytes)
#define SM_XHI  0
#define SM_XLO  (TILE_B)
#define SM_WHI  (2 * TILE_B)
#define SM_WLO  (3 * TILE_B)
#define SM_ALPH (4 * TILE_B)                          // as[128][2], ad[128][2] floats
#define SM_TOT  (4 * TILE_B + 2048)                   // 141312

// ---------------- scratch: __device__ globals only (no allocations) ----------------
__device__ __align__(16) float g_h[(size_t)N_NODES * D];   // post-GEMM features
__device__ __align__(16) float g_o[(size_t)N_NODES * D];   // layer-1 output
__device__ __align__(16) unsigned short g_wthi[2][128 * XPAD]; // W^T hi bf16 per layer
__device__ __align__(16) unsigned short g_wtlo[2][128 * XPAD]; // W^T lo bf16 per layer
__device__ float g_as[N_NODES];
__device__ float g_ad[N_NODES];
__device__ float g_ew[E_TOT];         // unnormalized edge weights
__device__ int   g_deg[N_NODES];      // self-zeroing each pass (starts 0)
__device__ int   g_incl[N_NODES];     // inclusive per-block scan
__device__ int   g_bsum[NB];
__device__ int   g_rp[N_NODES + 1];   // CSR row_ptr (by dst)
__device__ int   g_cur[N_NODES];      // scatter cursor (holds exclusive scan first)
__device__ int   g_col[E_TOT];        // src node per incoming edge
__device__ __align__(16) float g_part2[(size_t)AGG_BLKS * 128]; // layer-2 block partials
__device__ float g_part[128 * 128];

// ---------------- mma helper: m16n8k16 row.col f32.bf16.bf16.f32 ----------------
__device__ __forceinline__ void mma_bf16(float* c, uint32_t a0, uint32_t a1, uint32_t a2,
                                         uint32_t a3, uint32_t b0, uint32_t b1) {
    asm volatile(
        "mma.sync.aligned.m16n8k16.row.col.f32.bf16.bf16.f32 "
        "{%0,%1,%2,%3}, {%4,%5,%6,%7}, {%8,%9}, {%0,%1,%2,%3};"
        : "+f"(c[0]), "+f"(c[1]), "+f"(c[2]), "+f"(c[3])
        : "r"(a0), "r"(a1), "r"(a2), "r"(a3), "r"(b0), "r"(b1));
}
__device__ __forceinline__ uint32_t pack_bf16(float x, float y) {
    __nv_bfloat16 bx = __float2bfloat16(x), by = __float2bfloat16(y);
    unsigned short ux = *(unsigned short*)&bx, uy = *(unsigned short*)&by;
    return (uint32_t)ux | ((uint32_t)uy << 16);
}

// ---------------- CSR build (edge_index is int32: [src x E | dst x E]) ------------
__global__ void k_deg_count(const int* __restrict__ ei) {
    int e = blockIdx.x * blockDim.x + threadIdx.x;
    if (e < N_EDGES) {
        int d = ei[N_EDGES + e];
        if ((unsigned)d < N_NODES) atomicAdd(&g_deg[d], 1);
    }
}

// per-block inclusive scan of (deg+1); zeroes g_deg for the next pass
__global__ void __launch_bounds__(SCAN_B) k_scan1() {
    __shared__ int s[SCAN_B];
    int tl = threadIdx.x;
    int t  = blockIdx.x * SCAN_B + tl;
    int v  = 0;
    if (t < N_NODES) {
        v = g_deg[t] + 1;     // +1 self loop
        g_deg[t] = 0;         // self-zero for next replay
    }
    s[tl] = v;
    __syncthreads();
    #pragma unroll
    for (int off = 1; off < SCAN_B; off <<= 1) {
        int add = (tl >= off) ? s[tl - off] : 0;
        __syncthreads();
        s[tl] += add;
        __syncthreads();
    }
    if (t < N_NODES) { g_incl[t] = s[tl]; g_cur[t] = s[tl] - v; }
    if (tl == SCAN_B - 1) g_bsum[blockIdx.x] = s[tl];
}

// folds the 98-entry block-sum prefix into the final scan
__global__ void k_scan23() {
    __shared__ int spre[NB];
    if (threadIdx.x == 0) {
        int run = 0;
        #pragma unroll 2
        for (int i = 0; i < NB; i++) { int b = g_bsum[i]; spre[i] = run; run += b; }
    }
    __syncthreads();
    int t = blockIdx.x * blockDim.x + threadIdx.x;
    if (t < N_NODES) {
        int bp = spre[t >> 10];
        g_rp[t + 1] = g_incl[t] + bp;
        g_cur[t]   += bp;
        if (t == 0) g_rp[0] = 0;
    }
}

__global__ void k_scatter(const int* __restrict__ ei) {
    int e = blockIdx.x * blockDim.x + threadIdx.x;
    if (e >= E_TOT) return;
    int s, d;
    if (e < N_EDGES) { s = ei[e]; d = ei[N_EDGES + e]; }
    else             { s = e - N_EDGES; d = s; }
    if ((unsigned)s >= N_NODES || (unsigned)d >= N_NODES) return;
    int pos = atomicAdd(&g_cur[d], 1);
    g_col[pos] = s;
}

// ---------------- W split+transpose for BOTH layers in one launch -----------------
__global__ void k_wsplit(const float* __restrict__ W1, const float* __restrict__ W2) {
    int t = blockIdx.x * blockDim.x + threadIdx.x;
    if (t >= 2 * D * D) return;
    int layer = t >> 14;           // /(D*D)
    int r = t & (D * D - 1);
    int n = r >> 7, k = r & 127;
    const float* W = layer ? W2 : W1;
    float v = W[k * D + n];
    __nv_bfloat16 hb = __float2bfloat16(v);
    float hf = __bfloat162float(hb);
    __nv_bfloat16 lb = __float2bfloat16(v - hf);
    g_wthi[layer][n * XPAD + k] = *(unsigned short*)&hb;
    g_wtlo[layer][n * XPAD + k] = *(unsigned short*)&lb;
}

// ---------------- HMMA GEMM: H = X*W (split-2 bf16, fp32 accum) --------------------
__global__ void __launch_bounds__(256) k_gemm(
    const float* __restrict__ Xext, int use_ext, int wl,
    const float* __restrict__ avs, const float* __restrict__ avd)
{
    extern __shared__ unsigned char smem[];
    unsigned short* Xhi = (unsigned short*)(smem + SM_XHI);
    unsigned short* Xlo = (unsigned short*)(smem + SM_XLO);
    unsigned short* Whi = (unsigned short*)(smem + SM_WHI);
    unsigned short* Wlo = (unsigned short*)(smem + SM_WLO);
    float* as_s = (float*)(smem + SM_ALPH);          // [128][2]
    float* ad_s = (float*)(smem + SM_ALPH + 1024);   // [128][2]

    const int tid  = threadIdx.x;
    const int warp = tid >> 5;
    const int lane = tid & 31;
    const int lq   = lane & 3;
    const int lr   = lane >> 2;
    const int row0 = blockIdx.x * 128;
    const int mrow0 = (warp >> 1) * 32;
    const int ncol0 = (warp & 1) * 64;
    const float* X = use_ext ? Xext : g_o;

    {
        const float4* X4 = (const float4*)X;
        #pragma unroll
        for (int i = tid; i < 128 * 32; i += 256) {
            int r = i >> 5, c4 = i & 31;
            int gr = row0 + r;
            float4 v = (gr < N_NODES) ? X4[(size_t)gr * 32 + c4]
                                      : make_float4(0.f, 0.f, 0.f, 0.f);
            __nv_bfloat16 h0 = __float2bfloat16(v.x), h1 = __float2bfloat16(v.y);
            __nv_bfloat16 h2 = __float2bfloat16(v.z), h3 = __float2bfloat16(v.w);
            float f0 = __bfloat162float(h0), f1 = __bfloat162float(h1);
            float f2 = __bfloat162float(h2), f3 = __bfloat162float(h3);
            uint2 hw, lw;
            {
                unsigned short u0 = *(unsigned short*)&h0, u1 = *(unsigned short*)&h1;
                unsigned short u2 = *(unsigned short*)&h2, u3 = *(unsigned short*)&h3;
                hw.x = (uint32_t)u0 | ((uint32_t)u1 << 16);
                hw.y = (uint32_t)u2 | ((uint32_t)u3 << 16);
            }
            lw.x = pack_bf16(v.x - f0, v.y - f1);
            lw.y = pack_bf16(v.z - f2, v.w - f3);
            int off = r * XPAD + c4 * 4;
            *(uint2*)&Xhi[off] = hw;
            *(uint2*)&Xlo[off] = lw;
        }
    }
    {
        const uint4* wh = (const uint4*)g_wthi[wl];
        const uint4* wl4 = (const uint4*)g_wtlo[wl];
        uint4* sh = (uint4*)Whi;
        uint4* sl = (uint4*)Wlo;
        #pragma unroll
        for (int i = tid; i < TILE_B / 16; i += 256) { sh[i] = wh[i]; sl[i] = wl4[i]; }
    }
    __syncthreads();

    float acc[2][8][4];
    #pragma unroll
    for (int mt = 0; mt < 2; mt++)
        #pragma unroll
        for (int nt = 0; nt < 8; nt++)
            #pragma unroll
            for (int j = 0; j < 4; j++) acc[mt][nt][j] = 0.f;

    #pragma unroll
    for (int ks = 0; ks < 8; ks++) {
        const int kc = ks * 16 + lq * 2;
        uint32_t bh0[8], bh1[8], bl0[8], bl1[8];
        #pragma unroll
        for (int nt = 0; nt < 8; nt++) {
            int n = ncol0 + nt * 8 + lr;
            bh0[nt] = *(const uint32_t*)&Whi[n * XPAD + kc];
            bh1[nt] = *(const uint32_t*)&Whi[n * XPAD + kc + 8];
            bl0[nt] = *(const uint32_t*)&Wlo[n * XPAD + kc];
            bl1[nt] = *(const uint32_t*)&Wlo[n * XPAD + kc + 8];
        }
        #pragma unroll
        for (int mt = 0; mt < 2; mt++) {
            int r0 = mrow0 + mt * 16 + lr;
            uint32_t ah0 = *(const uint32_t*)&Xhi[r0 * XPAD + kc];
            uint32_t ah1 = *(const uint32_t*)&Xhi[(r0 + 8) * XPAD + kc];
            uint32_t ah2 = *(const uint32_t*)&Xhi[r0 * XPAD + kc + 8];
            uint32_t ah3 = *(const uint32_t*)&Xhi[(r0 + 8) * XPAD + kc + 8];
            uint32_t al0 = *(const uint32_t*)&Xlo[r0 * XPAD + kc];
            uint32_t al1 = *(const uint32_t*)&Xlo[(r0 + 8) * XPAD + kc];
            uint32_t al2 = *(const uint32_t*)&Xlo[r0 * XPAD + kc + 8];
            uint32_t al3 = *(const uint32_t*)&Xlo[(r0 + 8) * XPAD + kc + 8];
            #pragma unroll
            for (int nt = 0; nt < 8; nt++) {
                mma_bf16(acc[mt][nt], ah0, ah1, ah2, ah3, bh0[nt], bh1[nt]);
                mma_bf16(acc[mt][nt], ah0, ah1, ah2, ah3, bl0[nt], bl1[nt]);
                mma_bf16(acc[mt][nt], al0, al1, al2, al3, bh0[nt], bh1[nt]);
            }
        }
    }

    #pragma unroll
    for (int mt = 0; mt < 2; mt++) {
        int rl0 = mrow0 + mt * 16 + lr;
        int gr0 = row0 + rl0, gr1 = gr0 + 8;
        float ps0 = 0.f, ps1 = 0.f, pd0 = 0.f, pd1 = 0.f;
        #pragma unroll
        for (int nt = 0; nt < 8; nt++) {
            int c = ncol0 + nt * 8 + lq * 2;
            float s0 = avs[c], s1 = avs[c + 1];
            float d0 = avd[c], d1 = avd[c + 1];
            float* a = acc[mt][nt];
            ps0 += a[0] * s0 + a[1] * s1;
            pd0 += a[0] * d0 + a[1] * d1;
            ps1 += a[2] * s0 + a[3] * s1;
            pd1 += a[2] * d0 + a[3] * d1;
            if (gr0 < N_NODES) *(float2*)&g_h[(size_t)gr0 * D + c] = make_float2(a[0], a[1]);
            if (gr1 < N_NODES) *(float2*)&g_h[(size_t)gr1 * D + c] = make_float2(a[2], a[3]);
        }
        #pragma unroll
        for (int off = 1; off < 4; off <<= 1) {
            ps0 += __shfl_xor_sync(0xffffffffu, ps0, off);
            ps1 += __shfl_xor_sync(0xffffffffu, ps1, off);
            pd0 += __shfl_xor_sync(0xffffffffu, pd0, off);
            pd1 += __shfl_xor_sync(0xffffffffu, pd1, off);
        }
        if (lq == 0) {
            int half = warp & 1;
            as_s[rl0 * 2 + half] = ps0;       as_s[(rl0 + 8) * 2 + half] = ps1;
            ad_s[rl0 * 2 + half] = pd0;       ad_s[(rl0 + 8) * 2 + half] = pd1;
        }
    }
    __syncthreads();
    if (tid < 128) {
        int gr = row0 + tid;
        if (gr < N_NODES) {
            g_as[gr] = as_s[tid * 2] + as_s[tid * 2 + 1];
            g_ad[gr] = ad_s[tid * 2] + ad_s[tid * 2 + 1];
        }
    }
}

// ---------------- warp-per-node 2-pass softmax-aggregate (max-free, exact) --------
// mode 0: layer 1 -> relu, write g_o.  mode 1: layer 2 -> block partial sums only.
__global__ void __launch_bounds__(256) k_node_agg(int mode, const float* __restrict__ b)
{
    __shared__ float sb[8 * 128];
    int node = (blockIdx.x * blockDim.x + threadIdx.x) >> 5;
    int warp = threadIdx.x >> 5;
    int lane = threadIdx.x & 31;

    int beg = g_rp[node];
    int end = g_rp[node + 1];
    float ad = g_ad[node];

    // pass A: unnormalized weights -> g_ew, accumulate denominator
    float wsum = 0.f;
    for (int j = beg + lane; j < end; j += 32) {
        float e = g_as[g_col[j]] + ad;
        e = fmaxf(e, 0.f) + 0.2f * fminf(e, 0.f);
        float w = __expf(e);
        g_ew[j] = w;
        wsum += w;
    }
    #pragma unroll
    for (int off = 16; off; off >>= 1)
        wsum += __shfl_xor_sync(0xffffffffu, wsum, off);
    float inv = 1.f / wsum;
    __syncwarp();

    // pass B: feature accumulate (lane owns 4 columns); scale once at the end
    float4 acc = make_float4(0.f, 0.f, 0.f, 0.f);
    for (int j = beg; j < end; j++) {
        int   s = g_col[j];     // warp-uniform broadcast
        float w = g_ew[j];      // warp-uniform broadcast
        float4 hv = *(const float4*)&g_h[(size_t)s * D + lane * 4];
        acc.x = fmaf(w, hv.x, acc.x);
        acc.y = fmaf(w, hv.y, acc.y);
        acc.z = fmaf(w, hv.z, acc.z);
        acc.w = fmaf(w, hv.w, acc.w);
    }

    const float4 b4 = *(const float4*)&b[lane * 4];
    acc.x = fmaf(acc.x, inv, b4.x);
    acc.y = fmaf(acc.y, inv, b4.y);
    acc.z = fmaf(acc.z, inv, b4.z);
    acc.w = fmaf(acc.w, inv, b4.w);

    if (mode == 0) {
        acc.x = fmaxf(acc.x, 0.f); acc.y = fmaxf(acc.y, 0.f);
        acc.z = fmaxf(acc.z, 0.f); acc.w = fmaxf(acc.w, 0.f);
        *(float4*)&g_o[(size_t)node * D + lane * 4] = acc;
    } else {
        // layer 2: block-level partial sum for the final mean; g_o never written
        *(float4*)&sb[warp * 128 + lane * 4] = acc;
        __syncthreads();
        if (threadIdx.x < 128) {
            float s = 0.f;
            #pragma unroll
            for (int w = 0; w < 8; w++) s += sb[w * 128 + threadIdx.x];
            g_part2[(size_t)blockIdx.x * 128 + threadIdx.x] = s;
        }
    }
}

// ---------------- mean over nodes (from layer-2 block partials) -------------------
__global__ void k_meanA() {
    float s = 0.f;
    for (int r = blockIdx.x; r < AGG_BLKS; r += 128)
        s += g_part2[(size_t)r * 128 + threadIdx.x];
    g_part[blockIdx.x * 128 + threadIdx.x] = s;
}

__global__ void k_meanB(float* __restrict__ out) {
    int c = threadIdx.x;
    float s = 0.f;
    #pragma unroll 8
    for (int i = 0; i < 128; i++) s += g_part[i * 128 + c];
    out[c] = s * (1.0f / N_NODES);
}

// ---------------- driver: fork CSR build onto a side stream, join before agg1 -----
extern "C" void kernel_launch(void* const* d_in, const int* in_sizes, int n_in,
                              void* d_out, int out_size)
{
    const float* x   = (const float*)d_in[0];
    const int*   ei  = (const int*)d_in[1];      // int32: [src x E | dst x E]
    const float* W1  = (const float*)d_in[2];
    const float* as1 = (const float*)d_in[3];
    const float* ad1 = (const float*)d_in[4];
    const float* b1  = (const float*)d_in[5];
    const float* W2  = (const float*)d_in[6];
    const float* as2 = (const float*)d_in[7];
    const float* ad2 = (const float*)d_in[8];
    const float* b2  = (const float*)d_in[9];
    float* out = (float*)d_out;

    // one-time host-object setup (first call is the uncaptured correctness run;
    // no device memory is allocated here)
    static cudaStream_t s2 = nullptr;
    static cudaEvent_t ev_fork = nullptr, ev_csr = nullptr;
    if (s2 == nullptr) {
        cudaStreamCreateWithFlags(&s2, cudaStreamNonBlocking);
        cudaEventCreateWithFlags(&ev_fork, cudaEventDisableTiming);
        cudaEventCreateWithFlags(&ev_csr,  cudaEventDisableTiming);
        cudaFuncSetAttribute(k_gemm, cudaFuncAttributeMaxDynamicSharedMemorySize, SM_TOT);
    }

    // fork: side stream builds CSR while main stream does wsplit + layer-1 GEMM
    cudaEventRecord(ev_fork, 0);
    cudaStreamWaitEvent(s2, ev_fork, 0);

    k_deg_count<<<(N_EDGES + 255) / 256, 256, 0, s2>>>(ei);
    k_scan1    <<<NB, SCAN_B, 0, s2>>>();
    k_scan23   <<<(N_NODES + 255) / 256, 256, 0, s2>>>();
    k_scatter  <<<(E_TOT + 255) / 256, 256, 0, s2>>>(ei);
    cudaEventRecord(ev_csr, s2);

    k_wsplit<<<(2 * D * D + 255) / 256, 256>>>(W1, W2);
    k_gemm  <<<N_TILES, 256, SM_TOT>>>(x, 1, 0, as1, ad1);

    // join: aggregation needs both the CSR and layer-1 H/alphas
    cudaStreamWaitEvent(0, ev_csr, 0);

    // layer 1 aggregate -> g_o (relu)
    k_node_agg<<<AGG_BLKS, 256>>>(0, b1);

    // layer 2: g_o -> g_h -> block partials (g_o never re-written)
    k_gemm    <<<N_TILES, 256, SM_TOT>>>(nullptr, 0, 1, as2, ad2);
    k_node_agg<<<AGG_BLKS, 256>>>(1, b2);

    // mean over nodes -> d_out[128]
    k_meanA<<<128, 128>>>();
    k_meanB<<<1, 128>>>(out);
}